// round 1
// baseline (speedup 1.0000x reference)
#include <cuda_runtime.h>
#include <cuda_bf16.h>
#include <math.h>

// Problem dims
#define S_ 2048
#define B_ 64
#define I_ 256
#define H_ 512
#define ROWS_ (S_ * B_)          // 131072

// ---------------- scratch (no cudaMalloc allowed) ----------------
__device__ float g_buf0[(size_t)S_ * B_ * H_];   // layer0: xb0 -> y0 (in place)
__device__ float g_buf1[(size_t)S_ * B_ * H_];   // layer1: xb1 -> y1 (in place)
__device__ unsigned long long g_ctrs[2];

// ---------------- packed f32x2 FMA ----------------
__device__ __forceinline__ void fma2(float2& d, float2 a, float2 b) {
    asm volatile(
        "{\n\t"
        ".reg .b64 ra, rb, rd;\n\t"
        "mov.b64 ra, {%2, %3};\n\t"
        "mov.b64 rb, {%4, %5};\n\t"
        "mov.b64 rd, {%0, %1};\n\t"
        "fma.rn.f32x2 rd, ra, rb, rd;\n\t"
        "mov.b64 {%0, %1}, rd;\n\t"
        "}"
        : "+f"(d.x), "+f"(d.y)
        : "f"(a.x), "f"(a.y), "f"(b.x), "f"(b.y));
}

// ---------------- counter init (graph-replay safe reset) ----------------
__global__ void init_ctrs_kernel() {
    g_ctrs[0] = 0ULL;
    g_ctrs[1] = 0ULL;
}

// ---------------- projection GEMM: C = A @ W^T (+b1+b2), W masked ----------------
// A: [rows, K] row-major, W: [512, K], mask: [512, K] (0/1 int), C -> g_buf{which}
#define TM 64
#define TN 64
#define KC 64
#define SAST 66   // padded stride (floats): bank = (2*tx + k) % 32 -> conflict free

__global__ void __launch_bounds__(256) proj_kernel(
    const float* __restrict__ A_ext,       // nullptr => read g_buf0
    const float* __restrict__ W,
    const int*   __restrict__ Wmask,
    const float* __restrict__ bias1,
    const float* __restrict__ bias2,
    int K, int which_out)
{
    __shared__ float SA[TM * SAST];
    __shared__ float SW[TN * SAST];

    const float* A = A_ext ? A_ext : g_buf0;
    float* C = which_out ? g_buf1 : g_buf0;

    const int m0 = blockIdx.x * TM;
    const int n0 = blockIdx.y * TN;
    const int tid = threadIdx.x;
    const int tx = tid & 15;      // n sub-index
    const int ty = tid >> 4;      // m sub-index

    float2 acc[4][4];
#pragma unroll
    for (int i = 0; i < 4; i++)
#pragma unroll
        for (int j = 0; j < 4; j++) acc[i][j] = make_float2(0.f, 0.f);

    for (int kc = 0; kc < K; kc += KC) {
        // stage A tile: 64 rows x 64 k  (16 float4 per row)
#pragma unroll
        for (int t = tid; t < TM * 16; t += 256) {
            int r = t >> 4, q = t & 15;
            float4 v = *(const float4*)&A[(size_t)(m0 + r) * K + kc + 4 * q];
            int o = r * SAST + 4 * q;
            *(float2*)&SA[o]     = make_float2(v.x, v.y);
            *(float2*)&SA[o + 2] = make_float2(v.z, v.w);
        }
        // stage W tile (mask applied)
#pragma unroll
        for (int t = tid; t < TN * 16; t += 256) {
            int r = t >> 4, q = t & 15;
            size_t g = (size_t)(n0 + r) * K + kc + 4 * q;
            float4 v = *(const float4*)&W[g];
            int4  mm = *(const int4*)&Wmask[g];
            int o = r * SAST + 4 * q;
            SW[o]     = v.x * (float)mm.x;
            SW[o + 1] = v.y * (float)mm.y;
            SW[o + 2] = v.z * (float)mm.z;
            SW[o + 3] = v.w * (float)mm.w;
        }
        __syncthreads();

#pragma unroll 8
        for (int k = 0; k < KC; k += 2) {
            float2 a[4], w[4];
#pragma unroll
            for (int i = 0; i < 4; i++) a[i] = *(float2*)&SA[(ty + 16 * i) * SAST + k];
#pragma unroll
            for (int j = 0; j < 4; j++) w[j] = *(float2*)&SW[(tx + 16 * j) * SAST + k];
#pragma unroll
            for (int i = 0; i < 4; i++)
#pragma unroll
                for (int j = 0; j < 4; j++) fma2(acc[i][j], a[i], w[j]);
        }
        __syncthreads();
    }

    // epilogue
#pragma unroll
    for (int j = 0; j < 4; j++) {
        int n = n0 + tx + 16 * j;
        float bb = bias1[n] + bias2[n];
#pragma unroll
        for (int i = 0; i < 4; i++) {
            int m = m0 + ty + 16 * i;
            C[(size_t)m * H_ + n] = acc[i][j].x + acc[i][j].y + bb;
        }
    }
}

// ---------------- persistent recurrence kernel ----------------
// buf holds xb[s] on entry; we overwrite buf[s] with y[s] = tanh(xb[s] + y[s-1] @ Whh^T)
// grid = 128 CTAs (4 batch-groups x 32 h-groups), 128 threads, grid barrier per step.
#define NCTA 128
#define RTH  128
#define WST  514   // Ws stride: bank = (2*tx + k) % 32 -> conflict free
#define RNN_SMEM_BYTES ((16 * WST + 16 * H_) * 4)

__global__ void __launch_bounds__(RTH, 1) rnn_kernel(
    const float* __restrict__ Whh,
    const int*   __restrict__ mask,
    int layer)
{
    extern __shared__ float smem[];
    float* Ws = smem;                 // [16][WST]
    float* hs = smem + 16 * WST;      // [16][H_]

    float* buf = layer ? g_buf1 : g_buf0;
    unsigned long long* ctr = &g_ctrs[layer];

    const int bg = blockIdx.x >> 5;   // 0..3
    const int hg = blockIdx.x & 31;   // 0..31
    const int b0 = bg * 16;
    const int h0 = hg * 16;
    const int tid = threadIdx.x;
    const int tx = tid & 15;          // h_local
    const int bq = tid >> 4;          // 0..7 -> rows bq and bq+8

    // load masked Whh slice once: rows h0..h0+15, K=512
#pragma unroll
    for (int t = tid; t < 16 * 128; t += RTH) {
        int r = t >> 7, q = t & 127;
        size_t g = (size_t)(h0 + r) * H_ + 4 * q;
        float4 v = *(const float4*)&Whh[g];
        int4  mm = *(const int4*)&mask[g];
        int o = r * WST + 4 * q;
        Ws[o]     = v.x * (float)mm.x;
        Ws[o + 1] = v.y * (float)mm.y;
        Ws[o + 2] = v.z * (float)mm.z;
        Ws[o + 3] = v.w * (float)mm.w;
    }
    __syncthreads();

    const int row0 = b0 + bq;
    const int row1 = b0 + bq + 8;
    const int col  = h0 + tx;

    for (int s = 0; s < S_; ++s) {
        // stage h_prev tile (rows b0..b0+15, all 512)
        if (s > 0) {
            const float* src = buf + (size_t)(s - 1) * B_ * H_ + (size_t)b0 * H_;
#pragma unroll
            for (int t = tid; t < 16 * 128; t += RTH) {
                int r = t >> 7, q = t & 127;
                float4 v = *(const float4*)&src[r * H_ + 4 * q];
                *(float4*)&hs[r * H_ + 4 * q] = v;
            }
        }
        __syncthreads();

        float2 acc0 = make_float2(0.f, 0.f);
        float2 acc1 = make_float2(0.f, 0.f);
        if (s > 0) {
            const float* wrow = &Ws[tx * WST];
            const float* ar0  = &hs[bq * H_];
            const float* ar1  = &hs[(bq + 8) * H_];
#pragma unroll 8
            for (int k = 0; k < H_; k += 2) {
                float2 w  = *(const float2*)&wrow[k];
                float2 a0 = *(const float2*)&ar0[k];
                float2 a1 = *(const float2*)&ar1[k];
                fma2(acc0, a0, w);
                fma2(acc1, a1, w);
            }
        }

        size_t base = (size_t)s * B_ * H_;
        float xv0 = buf[base + (size_t)row0 * H_ + col];
        float xv1 = buf[base + (size_t)row1 * H_ + col];
        float o0 = tanhf(acc0.x + acc0.y + xv0);
        float o1 = tanhf(acc1.x + acc1.y + xv1);
        buf[base + (size_t)row0 * H_ + col] = o0;
        buf[base + (size_t)row1 * H_ + col] = o1;

        // grid barrier
        __syncthreads();
        if (tid == 0) {
            __threadfence();
            atomicAdd(ctr, 1ULL);
            unsigned long long target = (unsigned long long)(s + 1) * NCTA;
            unsigned long long cur;
            do {
                asm volatile("ld.acquire.gpu.u64 %0, [%1];"
                             : "=l"(cur) : "l"(ctr) : "memory");
            } while (cur < target);
        }
        __syncthreads();
    }
}

// ---------------- final copy ----------------
__global__ void copy_out_kernel(float* __restrict__ dst) {
    int i = blockIdx.x * blockDim.x + threadIdx.x;
    dst[i] = g_buf1[(size_t)(S_ - 1) * B_ * H_ + i];
}

// ---------------- launch ----------------
extern "C" void kernel_launch(void* const* d_in, const int* in_sizes, int n_in,
                              void* d_out, int out_size) {
    const float* x       = (const float*)d_in[0];
    const float* W_ih0   = (const float*)d_in[1];
    const float* W_hh0   = (const float*)d_in[2];
    const float* b_ih0   = (const float*)d_in[3];
    const float* b_hh0   = (const float*)d_in[4];
    const float* W_ih1   = (const float*)d_in[5];
    const float* W_hh1   = (const float*)d_in[6];
    const float* b_ih1   = (const float*)d_in[7];
    const float* b_hh1   = (const float*)d_in[8];
    const int*   m_ih0   = (const int*)d_in[9];
    const int*   m_hh0   = (const int*)d_in[10];
    const int*   m_ih1   = (const int*)d_in[11];
    const int*   m_hh1   = (const int*)d_in[12];
    float* out = (float*)d_out;

    static bool attr_set = false;
    if (!attr_set) {
        cudaFuncSetAttribute(rnn_kernel,
                             cudaFuncAttributeMaxDynamicSharedMemorySize,
                             RNN_SMEM_BYTES);
        attr_set = true;
    }

    init_ctrs_kernel<<<1, 1>>>();

    dim3 pgrid(ROWS_ / TM, H_ / TN);

    // layer 0 input projection: xb0 = x @ (Wih0*m)^T + b_ih0 + b_hh0 -> g_buf0
    proj_kernel<<<pgrid, 256>>>(x, W_ih0, m_ih0, b_ih0, b_hh0, I_, 0);
    // layer 0 recurrence (in place in g_buf0)
    rnn_kernel<<<NCTA, RTH, RNN_SMEM_BYTES>>>(W_hh0, m_hh0, 0);
    // layer 1 input projection: xb1 = y0 @ (Wih1*m)^T + b_ih1 + b_hh1 -> g_buf1
    proj_kernel<<<pgrid, 256>>>(nullptr, W_ih1, m_ih1, b_ih1, b_hh1, H_, 1);
    // layer 1 recurrence
    rnn_kernel<<<NCTA, RTH, RNN_SMEM_BYTES>>>(W_hh1, m_hh1, 1);
    // output = y1[S-1]
    copy_out_kernel<<<(B_ * H_) / 256, 256>>>(out);
}

// round 2
// speedup vs baseline: 1.1766x; 1.1766x over previous
#include <cuda_runtime.h>
#include <cuda_bf16.h>
#include <math.h>

// Problem dims
#define S_ 2048
#define B_ 64
#define I_ 256
#define H_ 512
#define ROWS_ (S_ * B_)          // 131072
#define BH_ (B_ * H_)

// ---------------- scratch (no cudaMalloc allowed) ----------------
__device__ float g_buf0[(size_t)S_ * B_ * H_];   // layer0: xb0 -> y0 (in place)
__device__ float g_buf1[(size_t)S_ * B_ * H_];   // layer1: xb1 -> y1 (in place)
__device__ unsigned g_ctr[2];
__device__ unsigned g_flag[2];

// ---------------- packed f32x2 FMA ----------------
__device__ __forceinline__ void fma2(float2& d, float2 a, float2 b) {
    asm volatile(
        "{\n\t"
        ".reg .b64 ra, rb, rd;\n\t"
        "mov.b64 ra, {%2, %3};\n\t"
        "mov.b64 rb, {%4, %5};\n\t"
        "mov.b64 rd, {%0, %1};\n\t"
        "fma.rn.f32x2 rd, ra, rb, rd;\n\t"
        "mov.b64 {%0, %1}, rd;\n\t"
        "}"
        : "+f"(d.x), "+f"(d.y)
        : "f"(a.x), "f"(a.y), "f"(b.x), "f"(b.y));
}

// ---------------- counter init (graph-replay safe reset) ----------------
__global__ void init_ctrs_kernel() {
    g_ctr[0] = 0u;  g_ctr[1] = 0u;
    g_flag[0] = 0u; g_flag[1] = 0u;
}

// ---------------- projection GEMM: C = A @ W^T (+b1+b2), W masked ----------------
#define TM 64
#define TN 64
#define KC 64
#define SAST 66   // padded stride (floats): bank = (2*tx + k) % 32 -> conflict free

__global__ void __launch_bounds__(256) proj_kernel(
    const float* __restrict__ A_ext,       // nullptr => read g_buf0
    const float* __restrict__ W,
    const int*   __restrict__ Wmask,
    const float* __restrict__ bias1,
    const float* __restrict__ bias2,
    int K, int which_out)
{
    __shared__ float SA[TM * SAST];
    __shared__ float SW[TN * SAST];

    const float* A = A_ext ? A_ext : g_buf0;
    float* C = which_out ? g_buf1 : g_buf0;

    const int m0 = blockIdx.x * TM;
    const int n0 = blockIdx.y * TN;
    const int tid = threadIdx.x;
    const int tx = tid & 15;      // n sub-index
    const int ty = tid >> 4;      // m sub-index

    float2 acc[4][4];
#pragma unroll
    for (int i = 0; i < 4; i++)
#pragma unroll
        for (int j = 0; j < 4; j++) acc[i][j] = make_float2(0.f, 0.f);

    for (int kc = 0; kc < K; kc += KC) {
#pragma unroll
        for (int t = tid; t < TM * 16; t += 256) {
            int r = t >> 4, q = t & 15;
            float4 v = *(const float4*)&A[(size_t)(m0 + r) * K + kc + 4 * q];
            int o = r * SAST + 4 * q;
            *(float2*)&SA[o]     = make_float2(v.x, v.y);
            *(float2*)&SA[o + 2] = make_float2(v.z, v.w);
        }
#pragma unroll
        for (int t = tid; t < TN * 16; t += 256) {
            int r = t >> 4, q = t & 15;
            size_t g = (size_t)(n0 + r) * K + kc + 4 * q;
            float4 v = *(const float4*)&W[g];
            int4  mm = *(const int4*)&Wmask[g];
            int o = r * SAST + 4 * q;
            SW[o]     = v.x * (float)mm.x;
            SW[o + 1] = v.y * (float)mm.y;
            SW[o + 2] = v.z * (float)mm.z;
            SW[o + 3] = v.w * (float)mm.w;
        }
        __syncthreads();

#pragma unroll 8
        for (int k = 0; k < KC; k += 2) {
            float2 a[4], w[4];
#pragma unroll
            for (int i = 0; i < 4; i++) a[i] = *(float2*)&SA[(ty + 16 * i) * SAST + k];
#pragma unroll
            for (int j = 0; j < 4; j++) w[j] = *(float2*)&SW[(tx + 16 * j) * SAST + k];
#pragma unroll
            for (int i = 0; i < 4; i++)
#pragma unroll
                for (int j = 0; j < 4; j++) fma2(acc[i][j], a[i], w[j]);
        }
        __syncthreads();
    }

#pragma unroll
    for (int j = 0; j < 4; j++) {
        int n = n0 + tx + 16 * j;
        float bb = bias1[n] + bias2[n];
#pragma unroll
        for (int i = 0; i < 4; i++) {
            int m = m0 + ty + 16 * i;
            C[(size_t)m * H_ + n] = acc[i][j].x + acc[i][j].y + bb;
        }
    }
}

// ---------------- persistent recurrence kernel ----------------
// buf holds xb[s] on entry; we overwrite buf[s] with y[s] = tanh(xb[s] + y[s-1] @ Whh^T)
// grid = 128 CTAs (4 batch-groups x 32 h-groups), 128 threads.
// Grid barrier: counter line (atomics only) + separate release-flag line (read-mostly).
#define NCTA 128
#define RTH  128
#define WST  514   // Ws stride: bank = (2*tx + k) % 32 -> conflict free (float2 loads)
#define RNN_SMEM_BYTES ((16 * WST + 16 * H_) * 4)

__global__ void __launch_bounds__(RTH, 1) rnn_kernel(
    const float* __restrict__ Whh,
    const int*   __restrict__ mask,
    int layer)
{
    extern __shared__ float smem[];
    float* Ws = smem;                 // [16][WST]
    float* hs = smem + 16 * WST;      // [16][H_]

    float* buf = layer ? g_buf1 : g_buf0;
    unsigned* ctr  = &g_ctr[layer];
    unsigned* flag = &g_flag[layer];

    const int bg = blockIdx.x >> 5;   // 0..3
    const int hg = blockIdx.x & 31;   // 0..31
    const int b0 = bg * 16;
    const int h0 = hg * 16;
    const int tid = threadIdx.x;
    const int tx = tid & 15;          // h_local
    const int bq = tid >> 4;          // 0..7 -> rows bq and bq+8

    // load masked Whh slice once: rows h0..h0+15, K=512
#pragma unroll
    for (int t = tid; t < 16 * 128; t += RTH) {
        int r = t >> 7, q = t & 127;
        size_t g = (size_t)(h0 + r) * H_ + 4 * q;
        float4 v = *(const float4*)&Whh[g];
        int4  mm = *(const int4*)&mask[g];
        int o = r * WST + 4 * q;
        Ws[o]     = v.x * (float)mm.x;
        Ws[o + 1] = v.y * (float)mm.y;
        Ws[o + 2] = v.z * (float)mm.z;
        Ws[o + 3] = v.w * (float)mm.w;
    }
    __syncthreads();

    const int row0 = b0 + bq;
    const int row1 = b0 + bq + 8;
    const int col  = h0 + tx;
    const size_t off0 = (size_t)row0 * H_ + col;
    const size_t off1 = (size_t)row1 * H_ + col;

    const float* wrow = &Ws[tx * WST];
    const float* ar0  = &hs[bq * H_];
    const float* ar1  = &hs[(bq + 8) * H_];

    // prefetch xb[0]
    float xv0 = __ldg(&buf[off0]);
    float xv1 = __ldg(&buf[off1]);

    for (int s = 0; s < S_; ++s) {
        // stage h_prev tile (rows b0..b0+15, all 512) -- y[s-1], valid after
        // last step's grid barrier
        if (s > 0) {
            const float* src = buf + (size_t)(s - 1) * BH_ + (size_t)b0 * H_;
#pragma unroll
            for (int t = tid; t < 16 * 128; t += RTH) {
                int r = t >> 7, q = t & 127;
                *(float4*)&hs[r * H_ + 4 * q] = *(const float4*)&src[r * H_ + 4 * q];
            }
        }
        __syncthreads();

        float2 c00 = make_float2(0.f, 0.f), c01 = make_float2(0.f, 0.f);
        float2 c10 = make_float2(0.f, 0.f), c11 = make_float2(0.f, 0.f);
        if (s > 0) {
#pragma unroll 4
            for (int k = 0; k < H_; k += 4) {
                float2 w01 = *(const float2*)&wrow[k];
                float2 w23 = *(const float2*)&wrow[k + 2];
                float4 a0  = *(const float4*)&ar0[k];
                float4 a1  = *(const float4*)&ar1[k];
                fma2(c00, make_float2(a0.x, a0.y), w01);
                fma2(c01, make_float2(a0.z, a0.w), w23);
                fma2(c10, make_float2(a1.x, a1.y), w01);
                fma2(c11, make_float2(a1.z, a1.w), w23);
            }
        }

        size_t base = (size_t)s * BH_;
        float o0 = tanhf(c00.x + c00.y + c01.x + c01.y + xv0);
        float o1 = tanhf(c10.x + c10.y + c11.x + c11.y + xv1);
        buf[base + off0] = o0;
        buf[base + off1] = o1;

        // prefetch xb[s+1] BEFORE the barrier -> DRAM latency hidden by spin
        if (s + 1 < S_) {
            xv0 = __ldg(&buf[base + BH_ + off0]);
            xv1 = __ldg(&buf[base + BH_ + off1]);
        }

        // grid barrier (split arrive / release lines)
        __syncthreads();   // all stores of this CTA issued
        if (tid == 0) {
            unsigned sv = (unsigned)(s + 1);
            unsigned old;
            asm volatile("atom.acq_rel.gpu.global.add.u32 %0, [%1], 1;"
                         : "=r"(old) : "l"(ctr) : "memory");
            if (old == sv * NCTA - 1) {
                asm volatile("st.release.gpu.global.u32 [%0], %1;"
                             :: "l"(flag), "r"(sv) : "memory");
            } else {
                unsigned f;
                do {
                    asm volatile("ld.acquire.gpu.global.u32 %0, [%1];"
                                 : "=r"(f) : "l"(flag) : "memory");
                } while (f < sv);
            }
        }
        __syncthreads();
    }
}

// ---------------- final copy ----------------
__global__ void copy_out_kernel(float* __restrict__ dst) {
    int i = blockIdx.x * blockDim.x + threadIdx.x;
    dst[i] = g_buf1[(size_t)(S_ - 1) * BH_ + i];
}

// ---------------- launch ----------------
extern "C" void kernel_launch(void* const* d_in, const int* in_sizes, int n_in,
                              void* d_out, int out_size) {
    const float* x       = (const float*)d_in[0];
    const float* W_ih0   = (const float*)d_in[1];
    const float* W_hh0   = (const float*)d_in[2];
    const float* b_ih0   = (const float*)d_in[3];
    const float* b_hh0   = (const float*)d_in[4];
    const float* W_ih1   = (const float*)d_in[5];
    const float* W_hh1   = (const float*)d_in[6];
    const float* b_ih1   = (const float*)d_in[7];
    const float* b_hh1   = (const float*)d_in[8];
    const int*   m_ih0   = (const int*)d_in[9];
    const int*   m_hh0   = (const int*)d_in[10];
    const int*   m_ih1   = (const int*)d_in[11];
    const int*   m_hh1   = (const int*)d_in[12];
    float* out = (float*)d_out;

    static bool attr_set = false;
    if (!attr_set) {
        cudaFuncSetAttribute(rnn_kernel,
                             cudaFuncAttributeMaxDynamicSharedMemorySize,
                             RNN_SMEM_BYTES);
        attr_set = true;
    }

    init_ctrs_kernel<<<1, 1>>>();

    dim3 pgrid(ROWS_ / TM, H_ / TN);

    proj_kernel<<<pgrid, 256>>>(x, W_ih0, m_ih0, b_ih0, b_hh0, I_, 0);
    rnn_kernel<<<NCTA, RTH, RNN_SMEM_BYTES>>>(W_hh0, m_hh0, 0);
    proj_kernel<<<pgrid, 256>>>(nullptr, W_ih1, m_ih1, b_ih1, b_hh1, H_, 1);
    rnn_kernel<<<NCTA, RTH, RNN_SMEM_BYTES>>>(W_hh1, m_hh1, 1);
    copy_out_kernel<<<(B_ * H_) / 256, 256>>>(out);
}

// round 3
// speedup vs baseline: 1.2402x; 1.0541x over previous
#include <cuda_runtime.h>
#include <math.h>

// Problem dims
#define S_ 2048
#define B_ 64
#define I_ 256
#define H_ 512
#define ROWS_ (S_ * B_)          // 131072
#define BH_ (B_ * H_)

// ---------------- scratch (no cudaMalloc allowed) ----------------
__device__ float g_buf0[(size_t)S_ * BH_];   // xb0 -> y0 (in place)
__device__ float g_buf1[(size_t)S_ * BH_];   // y1
__device__ float g_zero[16 * H_];            // stays zero (bss)
__device__ unsigned g_ctr[128];              // per-bgroup counter at bg*32 (128B apart)
__device__ unsigned g_flag[128];             // per-bgroup release flag at bg*32

// ---------------- packed f32x2 FMA ----------------
__device__ __forceinline__ void fma2(float2& d, float2 a, float2 b) {
    asm volatile(
        "{\n\t"
        ".reg .b64 ra, rb, rd;\n\t"
        "mov.b64 ra, {%2, %3};\n\t"
        "mov.b64 rb, {%4, %5};\n\t"
        "mov.b64 rd, {%0, %1};\n\t"
        "fma.rn.f32x2 rd, ra, rb, rd;\n\t"
        "mov.b64 {%0, %1}, rd;\n\t"
        "}"
        : "+f"(d.x), "+f"(d.y)
        : "f"(a.x), "f"(a.y), "f"(b.x), "f"(b.y));
}

__device__ __forceinline__ unsigned su32(const void* p) {
    return (unsigned)__cvta_generic_to_shared(p);
}
__device__ __forceinline__ void cp16(unsigned dst, const float* src) {
    asm volatile("cp.async.cg.shared.global [%0], [%1], 16;" :: "r"(dst), "l"(src));
}
#define CP_COMMIT() asm volatile("cp.async.commit_group;" ::: "memory")
#define CP_WAIT(n)  asm volatile("cp.async.wait_group %0;" :: "n"(n) : "memory")

// ---------------- counter init (graph-replay safe reset) ----------------
__global__ void init_ctrs_kernel() {
    int i = threadIdx.x;
    g_ctr[i] = 0u;
    g_flag[i] = 0u;
}

// ---------------- projection GEMM (layer 0 only): C = x @ W^T + b1 + b2 ----------------
#define TM 64
#define TN 64
#define KC 64
#define SAST 66

__global__ void __launch_bounds__(256) proj_kernel(
    const float* __restrict__ A,
    const float* __restrict__ W,
    const int*   __restrict__ Wmask,
    const float* __restrict__ bias1,
    const float* __restrict__ bias2,
    int K)
{
    __shared__ float SA[TM * SAST];
    __shared__ float SW[TN * SAST];

    float* C = g_buf0;
    const int m0 = blockIdx.x * TM;
    const int n0 = blockIdx.y * TN;
    const int tid = threadIdx.x;
    const int tx = tid & 15;
    const int ty = tid >> 4;

    float2 acc[4][4];
#pragma unroll
    for (int i = 0; i < 4; i++)
#pragma unroll
        for (int j = 0; j < 4; j++) acc[i][j] = make_float2(0.f, 0.f);

    for (int kc = 0; kc < K; kc += KC) {
#pragma unroll
        for (int t = tid; t < TM * 16; t += 256) {
            int r = t >> 4, q = t & 15;
            float4 v = *(const float4*)&A[(size_t)(m0 + r) * K + kc + 4 * q];
            int o = r * SAST + 4 * q;
            *(float2*)&SA[o]     = make_float2(v.x, v.y);
            *(float2*)&SA[o + 2] = make_float2(v.z, v.w);
        }
#pragma unroll
        for (int t = tid; t < TN * 16; t += 256) {
            int r = t >> 4, q = t & 15;
            size_t g = (size_t)(n0 + r) * K + kc + 4 * q;
            float4 v = *(const float4*)&W[g];
            int4  mm = *(const int4*)&Wmask[g];
            int o = r * SAST + 4 * q;
            SW[o]     = v.x * (float)mm.x;
            SW[o + 1] = v.y * (float)mm.y;
            SW[o + 2] = v.z * (float)mm.z;
            SW[o + 3] = v.w * (float)mm.w;
        }
        __syncthreads();

#pragma unroll 8
        for (int k = 0; k < KC; k += 2) {
            float2 a[4], w[4];
#pragma unroll
            for (int i = 0; i < 4; i++) a[i] = *(float2*)&SA[(ty + 16 * i) * SAST + k];
#pragma unroll
            for (int j = 0; j < 4; j++) w[j] = *(float2*)&SW[(tx + 16 * j) * SAST + k];
#pragma unroll
            for (int i = 0; i < 4; i++)
#pragma unroll
                for (int j = 0; j < 4; j++) fma2(acc[i][j], a[i], w[j]);
        }
        __syncthreads();
    }

#pragma unroll
    for (int j = 0; j < 4; j++) {
        int n = n0 + tx + 16 * j;
        float bb = bias1[n] + bias2[n];
#pragma unroll
        for (int i = 0; i < 4; i++) {
            int m = m0 + ty + 16 * i;
            C[(size_t)m * H_ + n] = acc[i][j].x + acc[i][j].y + bb;
        }
    }
}

// ---------------- fused 2-layer pipelined recurrence ----------------
// grid step t: L0 computes y0[t] (t<S_), L1 computes y1[t-1] (t>=1).
// 128 CTAs = 4 batch-groups x 32 h-groups; barrier is per batch-group (32 CTAs).
#define NCTA 128
#define RTH  128
#define GSZ  32
#define WST  514            // weight tile stride: conflict-free float2 reads
#define HST  520            // h tile stride: 16B-aligned rows, bank shift 8/row
#define SM_W0 0
#define SM_W1 (16 * WST)
#define SM_W2 (32 * WST)
#define SM_H0 (48 * WST)
#define SM_H1 (SM_H0 + 16 * HST)
#define SMEM_FLOATS (SM_H1 + 16 * HST)
#define RNN_SMEM_BYTES (SMEM_FLOATS * 4)

// 2-row x 512-K dot products against one weight row (shared col)
__device__ __forceinline__ void gemm_tile(const float* __restrict__ wrow,
                                          const float* __restrict__ ar0,
                                          const float* __restrict__ ar1,
                                          float& s0, float& s1) {
    float2 c00 = make_float2(0.f, 0.f), c01 = make_float2(0.f, 0.f);
    float2 c10 = make_float2(0.f, 0.f), c11 = make_float2(0.f, 0.f);
#pragma unroll 4
    for (int k = 0; k < H_; k += 4) {
        float2 w01 = *(const float2*)&wrow[k];
        float2 w23 = *(const float2*)&wrow[k + 2];
        float4 a0  = *(const float4*)&ar0[k];
        float4 a1  = *(const float4*)&ar1[k];
        fma2(c00, make_float2(a0.x, a0.y), w01);
        fma2(c01, make_float2(a0.z, a0.w), w23);
        fma2(c10, make_float2(a1.x, a1.y), w01);
        fma2(c11, make_float2(a1.z, a1.w), w23);
    }
    s0 = c00.x + c00.y + c01.x + c01.y;
    s1 = c10.x + c10.y + c11.x + c11.y;
}

__global__ void __launch_bounds__(RTH, 1) rnn_pipe_kernel(
    const float* __restrict__ Whh0, const int* __restrict__ m_hh0,
    const float* __restrict__ Wih1, const int* __restrict__ m_ih1,
    const float* __restrict__ Whh1, const int* __restrict__ m_hh1,
    const float* __restrict__ b_ih1, const float* __restrict__ b_hh1)
{
    extern __shared__ float smem[];

    const int bg = blockIdx.x >> 5;   // 0..3
    const int hg = blockIdx.x & 31;   // 0..31
    const int b0 = bg * 16;
    const int h0 = hg * 16;
    const int tid = threadIdx.x;
    const int tx = tid & 15;          // h_local (output col)
    const int bq = tid >> 4;          // 0..7 -> batch rows bq, bq+8

    unsigned* ctr  = &g_ctr[bg * GSZ];
    unsigned* flag = &g_flag[bg * GSZ];

    // ---- load 3 masked weight tiles (rows h0..h0+15, K=512) ----
    {
        const float* Ws[3] = { Whh0, Wih1, Whh1 };
        const int*   Ms[3] = { m_hh0, m_ih1, m_hh1 };
        const int    Os[3] = { SM_W0, SM_W1, SM_W2 };
#pragma unroll
        for (int w = 0; w < 3; w++) {
            float* dst = smem + Os[w];
            for (int t = tid; t < 16 * 128; t += RTH) {
                int r = t >> 7, q = t & 127;
                size_t g = (size_t)(h0 + r) * H_ + 4 * q;
                float4 v = *(const float4*)&Ws[w][g];
                int4  mm = *(const int4*)&Ms[w][g];
                int o = r * WST + 4 * q;
                dst[o]     = v.x * (float)mm.x;
                dst[o + 1] = v.y * (float)mm.y;
                dst[o + 2] = v.z * (float)mm.z;
                dst[o + 3] = v.w * (float)mm.w;
            }
        }
    }
    __syncthreads();

    const int row0 = b0 + bq;
    const int row1 = b0 + bq + 8;
    const int col  = h0 + tx;
    const size_t off0 = (size_t)row0 * H_ + col;
    const size_t off1 = (size_t)row1 * H_ + col;

    const float* w0row = &smem[SM_W0 + tx * WST];
    const float* w1row = &smem[SM_W1 + tx * WST];
    const float* w2row = &smem[SM_W2 + tx * WST];
    const float* h0r0  = &smem[SM_H0 + bq * HST];
    const float* h0r1  = &smem[SM_H0 + (bq + 8) * HST];
    const float* h1r0  = &smem[SM_H1 + bq * HST];
    const float* h1r1  = &smem[SM_H1 + (bq + 8) * HST];

    const unsigned hs0_base = su32(&smem[SM_H0]);
    const unsigned hs1_base = su32(&smem[SM_H1]);

    float xv0 = __ldg(&g_buf0[off0]);
    float xv1 = __ldg(&g_buf0[off1]);
    const float bL1 = __ldg(&b_ih1[col]) + __ldg(&b_hh1[col]);

    for (int t = 0; t <= S_; ++t) {
        float g0 = 0.f, g1 = 0.f;

        if (t > 0) {
            // wait for all 32 CTAs of this batch-group to finish step t-1
            unsigned f;
            do {
                asm volatile("ld.acquire.gpu.global.u32 %0, [%1];"
                             : "=r"(f) : "l"(flag) : "memory");
            } while (f < (unsigned)t);

            // stage hs0 = y0[t-1] (16 rows x 512, contiguous 32KB)
            {
                const float* src = g_buf0 + (size_t)(t - 1) * BH_ + (size_t)b0 * H_;
#pragma unroll
                for (int i = 0; i < 16; i++) {
                    int idx = tid + i * RTH;       // 0..2047 (16B chunks)
                    int r = idx >> 7, q = idx & 127;
                    cp16(hs0_base + (unsigned)(r * HST + 4 * q) * 4, src + (size_t)idx * 4);
                }
            }
            CP_COMMIT();
            // stage hs1 = y1[t-2] (zeros at t==1)
            {
                const float* src = (t >= 2)
                    ? g_buf1 + (size_t)(t - 2) * BH_ + (size_t)b0 * H_
                    : g_zero;
#pragma unroll
                for (int i = 0; i < 16; i++) {
                    int idx = tid + i * RTH;
                    int r = idx >> 7, q = idx & 127;
                    cp16(hs1_base + (unsigned)(r * HST + 4 * q) * 4, src + (size_t)idx * 4);
                }
            }
            CP_COMMIT();

            CP_WAIT(1);            // hs0 ready; hs1 still in flight
            __syncthreads();

            if (t < S_) gemm_tile(w0row, h0r0, h0r1, g0, g1);   // y0[t] recurrent term
            float p0, p1;
            gemm_tile(w1row, h0r0, h0r1, p0, p1);               // xb1[t-1] on the fly

            CP_WAIT(0);            // hs1 ready
            __syncthreads();

            float q0, q1;
            gemm_tile(w2row, h1r0, h1r1, q0, q1);               // y1 recurrent term

            float y1a = tanhf(p0 + q0 + bL1);
            float y1b = tanhf(p1 + q1 + bL1);
            g_buf1[(size_t)(t - 1) * BH_ + off0] = y1a;
            g_buf1[(size_t)(t - 1) * BH_ + off1] = y1b;
        }

        if (t < S_) {
            float y0a = tanhf(g0 + xv0);
            float y0b = tanhf(g1 + xv1);
            g_buf0[(size_t)t * BH_ + off0] = y0a;
            g_buf0[(size_t)t * BH_ + off1] = y0b;
            if (t + 1 < S_) {   // prefetch xb0[t+1]; lands during barrier spin
                xv0 = __ldg(&g_buf0[(size_t)(t + 1) * BH_ + off0]);
                xv1 = __ldg(&g_buf0[(size_t)(t + 1) * BH_ + off1]);
            }
        }

        // group barrier arrival
        __syncthreads();
        if (tid == 0) {
            unsigned old;
            asm volatile("atom.acq_rel.gpu.global.add.u32 %0, [%1], 1;"
                         : "=r"(old) : "l"(ctr) : "memory");
            if (old == (unsigned)((t + 1) * GSZ - 1)) {
                asm volatile("st.release.gpu.global.u32 [%0], %1;"
                             :: "l"(flag), "r"((unsigned)(t + 1)) : "memory");
            }
        }
    }
}

// ---------------- final copy ----------------
__global__ void copy_out_kernel(float* __restrict__ dst) {
    int i = blockIdx.x * blockDim.x + threadIdx.x;
    dst[i] = g_buf1[(size_t)(S_ - 1) * BH_ + i];
}

// ---------------- launch ----------------
extern "C" void kernel_launch(void* const* d_in, const int* in_sizes, int n_in,
                              void* d_out, int out_size) {
    const float* x       = (const float*)d_in[0];
    const float* W_ih0   = (const float*)d_in[1];
    const float* W_hh0   = (const float*)d_in[2];
    const float* b_ih0   = (const float*)d_in[3];
    const float* b_hh0   = (const float*)d_in[4];
    const float* W_ih1   = (const float*)d_in[5];
    const float* W_hh1   = (const float*)d_in[6];
    const float* b_ih1   = (const float*)d_in[7];
    const float* b_hh1   = (const float*)d_in[8];
    const int*   m_ih0   = (const int*)d_in[9];
    const int*   m_hh0   = (const int*)d_in[10];
    const int*   m_ih1   = (const int*)d_in[11];
    const int*   m_hh1   = (const int*)d_in[12];
    float* out = (float*)d_out;

    static bool attr_set = false;
    if (!attr_set) {
        cudaFuncSetAttribute(rnn_pipe_kernel,
                             cudaFuncAttributeMaxDynamicSharedMemorySize,
                             RNN_SMEM_BYTES);
        attr_set = true;
    }

    init_ctrs_kernel<<<1, 128>>>();

    // layer-0 input projection: xb0 = x @ (Wih0*m)^T + b_ih0 + b_hh0 -> g_buf0
    dim3 pgrid(ROWS_ / TM, H_ / TN);
    proj_kernel<<<pgrid, 256>>>(x, W_ih0, m_ih0, b_ih0, b_hh0, I_);

    // fused pipelined 2-layer recurrence (includes layer-1 input projection)
    rnn_pipe_kernel<<<NCTA, RTH, RNN_SMEM_BYTES>>>(
        W_hh0, m_hh0, W_ih1, m_ih1, W_hh1, m_hh1, b_ih1, b_hh1);

    copy_out_kernel<<<(BH_) / 256, 256>>>(out);
}

// round 4
// speedup vs baseline: 2.1206x; 1.7098x over previous
#include <cuda_runtime.h>
#include <math.h>

// Problem dims
#define S_ 2048
#define B_ 64
#define I_ 256
#define H_ 512
#define ROWS_ (S_ * B_)          // 131072
#define BH_ (B_ * H_)

// ---------------- scratch (no cudaMalloc allowed) ----------------
__device__ float g_buf0[(size_t)S_ * BH_];   // xb0 -> y0 (in place)
__device__ float g_buf1[(size_t)S_ * BH_];   // y1
__device__ float g_zero[16 * H_];            // stays zero (bss)
__device__ unsigned g_ctr[128];              // per-bgroup counter at bg*32
__device__ unsigned g_flag[128];             // per-bgroup release flag at bg*32

// ---------------- packed f32x2 FMA ----------------
__device__ __forceinline__ void fma2(float2& d, float2 a, float2 b) {
    asm volatile(
        "{\n\t"
        ".reg .b64 ra, rb, rd;\n\t"
        "mov.b64 ra, {%2, %3};\n\t"
        "mov.b64 rb, {%4, %5};\n\t"
        "mov.b64 rd, {%0, %1};\n\t"
        "fma.rn.f32x2 rd, ra, rb, rd;\n\t"
        "mov.b64 {%0, %1}, rd;\n\t"
        "}"
        : "+f"(d.x), "+f"(d.y)
        : "f"(a.x), "f"(a.y), "f"(b.x), "f"(b.y));
}
__device__ __forceinline__ void fma4(float2& acc, float4 a, float4 w) {
    fma2(acc, make_float2(a.x, a.y), make_float2(w.x, w.y));
    fma2(acc, make_float2(a.z, a.w), make_float2(w.z, w.w));
}

__device__ __forceinline__ unsigned su32(const void* p) {
    return (unsigned)__cvta_generic_to_shared(p);
}
__device__ __forceinline__ void cp16(unsigned dst, const float* src) {
    asm volatile("cp.async.cg.shared.global [%0], [%1], 16;" :: "r"(dst), "l"(src));
}
#define CP_COMMIT() asm volatile("cp.async.commit_group;" ::: "memory")
#define CP_WAIT(n)  asm volatile("cp.async.wait_group %0;" :: "n"(n) : "memory")

// ---------------- counter init (graph-replay safe reset) ----------------
__global__ void init_ctrs_kernel() {
    int i = threadIdx.x;
    g_ctr[i] = 0u;
    g_flag[i] = 0u;
}

// ---------------- projection GEMM (layer 0 only) ----------------
#define TM 64
#define TN 64
#define KC 64
#define SAST 66

__global__ void __launch_bounds__(256) proj_kernel(
    const float* __restrict__ A,
    const float* __restrict__ W,
    const int*   __restrict__ Wmask,
    const float* __restrict__ bias1,
    const float* __restrict__ bias2,
    int K)
{
    __shared__ float SA[TM * SAST];
    __shared__ float SW[TN * SAST];

    float* C = g_buf0;
    const int m0 = blockIdx.x * TM;
    const int n0 = blockIdx.y * TN;
    const int tid = threadIdx.x;
    const int tx = tid & 15;
    const int ty = tid >> 4;

    float2 acc[4][4];
#pragma unroll
    for (int i = 0; i < 4; i++)
#pragma unroll
        for (int j = 0; j < 4; j++) acc[i][j] = make_float2(0.f, 0.f);

    for (int kc = 0; kc < K; kc += KC) {
#pragma unroll
        for (int t = tid; t < TM * 16; t += 256) {
            int r = t >> 4, q = t & 15;
            float4 v = *(const float4*)&A[(size_t)(m0 + r) * K + kc + 4 * q];
            int o = r * SAST + 4 * q;
            *(float2*)&SA[o]     = make_float2(v.x, v.y);
            *(float2*)&SA[o + 2] = make_float2(v.z, v.w);
        }
#pragma unroll
        for (int t = tid; t < TN * 16; t += 256) {
            int r = t >> 4, q = t & 15;
            size_t g = (size_t)(n0 + r) * K + kc + 4 * q;
            float4 v = *(const float4*)&W[g];
            int4  mm = *(const int4*)&Wmask[g];
            int o = r * SAST + 4 * q;
            SW[o]     = v.x * (float)mm.x;
            SW[o + 1] = v.y * (float)mm.y;
            SW[o + 2] = v.z * (float)mm.z;
            SW[o + 3] = v.w * (float)mm.w;
        }
        __syncthreads();

#pragma unroll 8
        for (int k = 0; k < KC; k += 2) {
            float2 a[4], w[4];
#pragma unroll
            for (int i = 0; i < 4; i++) a[i] = *(float2*)&SA[(ty + 16 * i) * SAST + k];
#pragma unroll
            for (int j = 0; j < 4; j++) w[j] = *(float2*)&SW[(tx + 16 * j) * SAST + k];
#pragma unroll
            for (int i = 0; i < 4; i++)
#pragma unroll
                for (int j = 0; j < 4; j++) fma2(acc[i][j], a[i], w[j]);
        }
        __syncthreads();
    }

#pragma unroll
    for (int j = 0; j < 4; j++) {
        int n = n0 + tx + 16 * j;
        float bb = bias1[n] + bias2[n];
#pragma unroll
        for (int i = 0; i < 4; i++) {
            int m = m0 + ty + 16 * i;
            C[(size_t)m * H_ + n] = acc[i][j].x + acc[i][j].y + bb;
        }
    }
}

// ---------------- fused 2-layer pipelined recurrence, weights in registers ----
// 128 CTAs = 4 bg x 32 hg.  256 threads: tx = tid&7 (col pair), ks = tid>>3
// (k-slice of 16).  Each thread holds wr[3][2 cols][16 k] = 96 floats in regs.
// Per step: stream 16 hs rows from smem (broadcast LDS.128), fma vs registers,
// write 16-k partial sums to padded smem, then a 32-way reduction per output.
#define NCTA 128
#define RTH  256
#define GSZ  32
#define HST  520            // hs row stride (floats)
#define RST  272            // red ks stride: (272/2)%32==8 -> conflict-free STS.64
#define RED_G (32 * RST)    // floats per gemm in red buffer
#define HS0_OFF 0
#define HS1_OFF (16 * HST)
#define RED_OFF (32 * HST)
#define SMEM_FLOATS (RED_OFF + 3 * RED_G)
#define RNN_SMEM_BYTES (SMEM_FLOATS * 4)   // 171008 B

__global__ void __launch_bounds__(RTH, 1) rnn_pipe_kernel(
    const float* __restrict__ Whh0, const int* __restrict__ m_hh0,
    const float* __restrict__ Wih1, const int* __restrict__ m_ih1,
    const float* __restrict__ Whh1, const int* __restrict__ m_hh1,
    const float* __restrict__ b_ih1, const float* __restrict__ b_hh1)
{
    extern __shared__ float smem[];
    float* hs0 = smem + HS0_OFF;     // [16][HST]
    float* hs1 = smem + HS1_OFF;     // [16][HST]
    float* red = smem + RED_OFF;     // [3][32][RST]

    const int bg = blockIdx.x >> 5;   // 0..3
    const int hg = blockIdx.x & 31;   // 0..31
    const int b0 = bg * 16;
    const int h0 = hg * 16;
    const int tid = threadIdx.x;
    const int tx = tid & 7;           // col pair index
    const int ks = tid >> 3;          // 0..31, k-slice of 16
    const int k0 = ks * 16;

    unsigned* ctr  = &g_ctr[bg * GSZ];
    unsigned* flag = &g_flag[bg * GSZ];

    // ---- permanent register weights: wr[gemm][col][q of 4 k-floats] ----
    float4 wr[3][2][4];
    {
        const float* Wp[3] = { Whh0, Wih1, Whh1 };
        const int*   Mp[3] = { m_hh0, m_ih1, m_hh1 };
#pragma unroll
        for (int g = 0; g < 3; g++)
#pragma unroll
            for (int c = 0; c < 2; c++) {
                size_t ro = (size_t)(h0 + 2 * tx + c) * H_ + k0;
#pragma unroll
                for (int q = 0; q < 4; q++) {
                    float4 v = *(const float4*)&Wp[g][ro + 4 * q];
                    int4  mm = *(const int4*)&Mp[g][ro + 4 * q];
                    wr[g][c][q] = make_float4(v.x * (float)mm.x, v.y * (float)mm.y,
                                              v.z * (float)mm.z, v.w * (float)mm.w);
                }
            }
    }

    // output mapping: thread tid -> output (row orow, col ocol) of the 16x16 tile
    const int orow = tid >> 4;
    const int ocol = tid & 15;
    const size_t offO = (size_t)(b0 + orow) * H_ + (h0 + ocol);
    const float bL1 = __ldg(&b_ih1[h0 + ocol]) + __ldg(&b_hh1[h0 + ocol]);
    float xv = __ldg(&g_buf0[offO]);

    const unsigned hs0_b = su32(hs0);
    const unsigned hs1_b = su32(hs1);
    const int sts0 = 0 * RED_G + ks * RST + 2 * tx;   // + r*16 at use
    const int sts1 = 1 * RED_G + ks * RST + 2 * tx;
    const int sts2 = 2 * RED_G + ks * RST + 2 * tx;

    for (int t = 0; t <= S_; ++t) {
        if (t > 0) {
            // wait for step t-1 of this batch-group
            unsigned f;
            do {
                asm volatile("ld.acquire.gpu.global.u32 %0, [%1];"
                             : "=r"(f) : "l"(flag) : "memory");
            } while (f < (unsigned)t);

            // stage hs0 = y0[t-1]
            {
                const float* src = g_buf0 + (size_t)(t - 1) * BH_ + (size_t)b0 * H_;
#pragma unroll
                for (int i = 0; i < 8; i++) {
                    int idx = tid + i * RTH;             // 0..2047 16B chunks
                    int r = idx >> 7, q = idx & 127;
                    cp16(hs0_b + (unsigned)(r * HST + 4 * q) * 4u, src + (size_t)idx * 4);
                }
            }
            CP_COMMIT();
            // stage hs1 = y1[t-2] (zeros at t==1)
            {
                const float* src = (t >= 2)
                    ? g_buf1 + (size_t)(t - 2) * BH_ + (size_t)b0 * H_ : g_zero;
#pragma unroll
                for (int i = 0; i < 8; i++) {
                    int idx = tid + i * RTH;
                    int r = idx >> 7, q = idx & 127;
                    cp16(hs1_b + (unsigned)(r * HST + 4 * q) * 4u, src + (size_t)idx * 4);
                }
            }
            CP_COMMIT();

            CP_WAIT(1);              // hs0 ready
            __syncthreads();

            // gemm0 (Whh0) + gemm1 (Wih1) over hs0 rows
#pragma unroll 4
            for (int r = 0; r < 16; r++) {
                const float* ap = &hs0[r * HST + k0];
                float4 a0 = *(const float4*)&ap[0];
                float4 a1 = *(const float4*)&ap[4];
                float4 a2 = *(const float4*)&ap[8];
                float4 a3 = *(const float4*)&ap[12];
                float2 p00 = make_float2(0.f, 0.f), p01 = make_float2(0.f, 0.f);
                float2 p10 = make_float2(0.f, 0.f), p11 = make_float2(0.f, 0.f);
                fma4(p00, a0, wr[0][0][0]); fma4(p01, a0, wr[0][1][0]);
                fma4(p10, a0, wr[1][0][0]); fma4(p11, a0, wr[1][1][0]);
                fma4(p00, a1, wr[0][0][1]); fma4(p01, a1, wr[0][1][1]);
                fma4(p10, a1, wr[1][0][1]); fma4(p11, a1, wr[1][1][1]);
                fma4(p00, a2, wr[0][0][2]); fma4(p01, a2, wr[0][1][2]);
                fma4(p10, a2, wr[1][0][2]); fma4(p11, a2, wr[1][1][2]);
                fma4(p00, a3, wr[0][0][3]); fma4(p01, a3, wr[0][1][3]);
                fma4(p10, a3, wr[1][0][3]); fma4(p11, a3, wr[1][1][3]);
                *(float2*)&red[sts0 + r * 16] =
                    make_float2(p00.x + p00.y, p01.x + p01.y);
                *(float2*)&red[sts1 + r * 16] =
                    make_float2(p10.x + p10.y, p11.x + p11.y);
            }

            CP_WAIT(0);              // hs1 ready
            __syncthreads();

            // gemm2 (Whh1) over hs1 rows
#pragma unroll 4
            for (int r = 0; r < 16; r++) {
                const float* ap = &hs1[r * HST + k0];
                float4 a0 = *(const float4*)&ap[0];
                float4 a1 = *(const float4*)&ap[4];
                float4 a2 = *(const float4*)&ap[8];
                float4 a3 = *(const float4*)&ap[12];
                float2 p20 = make_float2(0.f, 0.f), p21 = make_float2(0.f, 0.f);
                fma4(p20, a0, wr[2][0][0]); fma4(p21, a0, wr[2][1][0]);
                fma4(p20, a1, wr[2][0][1]); fma4(p21, a1, wr[2][1][1]);
                fma4(p20, a2, wr[2][0][2]); fma4(p21, a2, wr[2][1][2]);
                fma4(p20, a3, wr[2][0][3]); fma4(p21, a3, wr[2][1][3]);
                *(float2*)&red[sts2 + r * 16] =
                    make_float2(p20.x + p20.y, p21.x + p21.y);
            }
            __syncthreads();
        }

        // 32-way k-slice reduction (1 output per thread)
        float s0 = 0.f, s1 = 0.f, s2 = 0.f;
        if (t > 0) {
#pragma unroll
            for (int k = 0; k < 32; k++) {
                s0 += red[0 * RED_G + k * RST + tid];
                s1 += red[1 * RED_G + k * RST + tid];
                s2 += red[2 * RED_G + k * RST + tid];
            }
        }

        if (t < S_) {
            float y0 = tanhf(s0 + xv);
            g_buf0[(size_t)t * BH_ + offO] = y0;
            if (t + 1 < S_)
                xv = __ldg(&g_buf0[(size_t)(t + 1) * BH_ + offO]);
        }
        if (t > 0) {
            float y1 = tanhf(s1 + s2 + bL1);
            g_buf1[(size_t)(t - 1) * BH_ + offO] = y1;
        }

        // group barrier arrival
        __syncthreads();
        if (tid == 0) {
            unsigned old;
            asm volatile("atom.acq_rel.gpu.global.add.u32 %0, [%1], 1;"
                         : "=r"(old) : "l"(ctr) : "memory");
            if (old == (unsigned)((t + 1) * GSZ - 1)) {
                asm volatile("st.release.gpu.global.u32 [%0], %1;"
                             :: "l"(flag), "r"((unsigned)(t + 1)) : "memory");
            }
        }
    }
}

// ---------------- final copy ----------------
__global__ void copy_out_kernel(float* __restrict__ dst) {
    int i = blockIdx.x * blockDim.x + threadIdx.x;
    dst[i] = g_buf1[(size_t)(S_ - 1) * BH_ + i];
}

// ---------------- launch ----------------
extern "C" void kernel_launch(void* const* d_in, const int* in_sizes, int n_in,
                              void* d_out, int out_size) {
    const float* x       = (const float*)d_in[0];
    const float* W_ih0   = (const float*)d_in[1];
    const float* W_hh0   = (const float*)d_in[2];
    const float* b_ih0   = (const float*)d_in[3];
    const float* b_hh0   = (const float*)d_in[4];
    const float* W_ih1   = (const float*)d_in[5];
    const float* W_hh1   = (const float*)d_in[6];
    const float* b_ih1   = (const float*)d_in[7];
    const float* b_hh1   = (const float*)d_in[8];
    const int*   m_ih0   = (const int*)d_in[9];
    const int*   m_hh0   = (const int*)d_in[10];
    const int*   m_ih1   = (const int*)d_in[11];
    const int*   m_hh1   = (const int*)d_in[12];
    float* out = (float*)d_out;

    static bool attr_set = false;
    if (!attr_set) {
        cudaFuncSetAttribute(rnn_pipe_kernel,
                             cudaFuncAttributeMaxDynamicSharedMemorySize,
                             RNN_SMEM_BYTES);
        attr_set = true;
    }

    init_ctrs_kernel<<<1, 128>>>();

    dim3 pgrid(ROWS_ / TM, H_ / TN);
    proj_kernel<<<pgrid, 256>>>(x, W_ih0, m_ih0, b_ih0, b_hh0, I_);

    rnn_pipe_kernel<<<NCTA, RTH, RNN_SMEM_BYTES>>>(
        W_hh0, m_hh0, W_ih1, m_ih1, W_hh1, m_hh1, b_ih1, b_hh1);

    copy_out_kernel<<<(BH_) / 256, 256>>>(out);
}